// round 15
// baseline (speedup 1.0000x reference)
#include <cuda_runtime.h>
#include <cstdint>

#define Bn 2048
#define Sn 128
#define Hn 128
#define En 128

// ---------------- device scratch ----------------
__device__ float d_embedded[Bn*Sn*En];
__device__ float d_enc[Bn*Sn*Hn];
__device__ float d_tmp[Bn*Sn*Hn];
__device__ float d_gref[Bn*Hn*Sn];
__device__ float d_pref[Bn*Hn*Sn];
__device__ float d_h[Bn*Hn];
__device__ float d_c[Bn*Hn];
__device__ float d_gates[Bn*4*Hn];
__device__ float d_qg[Bn*Hn];
__device__ float d_q2[Bn*Hn];
__device__ float d_qp[Bn*Hn];
__device__ float d_decin[Bn*En];
__device__ unsigned char d_mask[Bn*Sn];
__device__ float d_Wenc[256*512];
__device__ float d_Wdec[256*512];
__device__ float d_benc[512];
__device__ float d_bdec[512];
__device__ float d_WqgT[128*128];
__device__ float d_WqpT[128*128];
__device__ float d_WgrT[128*128];
__device__ float d_WprT[128*128];
__device__ unsigned d_bar_arrive = 0;
__device__ unsigned d_bar_gen = 0;

// ---------------- helpers ----------------
__device__ __forceinline__ float sigf(float x){ return 1.0f/(1.0f+expf(-x)); }

__device__ __forceinline__ void threefry2x32(unsigned k0, unsigned k1,
                                             unsigned x0, unsigned x1,
                                             unsigned &o0, unsigned &o1)
{
    unsigned ks2 = k0 ^ k1 ^ 0x1BD11BDAu;
    x0 += k0; x1 += k1;
#define TF_R(r) { x0 += x1; x1 = (x1 << (r)) | (x1 >> (32-(r))); x1 ^= x0; }
    TF_R(13) TF_R(15) TF_R(26) TF_R(6)
    x0 += k1;  x1 += ks2 + 1u;
    TF_R(17) TF_R(29) TF_R(16) TF_R(24)
    x0 += ks2; x1 += k0 + 2u;
    TF_R(13) TF_R(15) TF_R(26) TF_R(6)
    x0 += k0;  x1 += k1 + 3u;
    TF_R(17) TF_R(29) TF_R(16) TF_R(24)
    x0 += k1;  x1 += ks2 + 4u;
    TF_R(13) TF_R(15) TF_R(26) TF_R(6)
    x0 += ks2; x1 += k0 + 5u;
#undef TF_R
    o0 = x0; o1 = x1;
}

// hardened grid barrier — all blocks resident (grid == #SMs)
__device__ __forceinline__ void grid_sync()
{
    __syncthreads();
    if (threadIdx.x == 0) {
        unsigned gen;
        asm volatile("ld.acquire.gpu.u32 %0, [%1];" : "=r"(gen)
                     : "l"(&d_bar_gen) : "memory");
        __threadfence();                       // release my block's writes
        unsigned prev = atomicAdd(&d_bar_arrive, 1u);
        if (prev == gridDim.x - 1) {
            atomicExch(&d_bar_arrive, 0u);
            asm volatile("st.release.gpu.u32 [%0], %1;" ::
                         "l"(&d_bar_gen), "r"(gen + 1u) : "memory");
        } else {
            unsigned cur;
            do {
                asm volatile("ld.acquire.gpu.u32 %0, [%1];" : "=r"(cur)
                             : "l"(&d_bar_gen) : "memory");
            } while (cur == gen);
        }
    }
    __syncthreads();
    __threadfence();   // order/invalidate so post-barrier loads are fresh
}

// ---------------- gemm phase: C = [A1|A2] * B + bias ----------------
__device__ void gemm_phase(
    const float* __restrict__ A1, int lda1,
    const float* __restrict__ A2, int lda2,
    const float* __restrict__ Bm, const float* __restrict__ bias,
    float* __restrict__ C, int ldc,
    int M, int N, int K1, int K2)
{
    __shared__ float As[64][17];
    __shared__ __align__(16) float Bs[16][64];
    const int tid = threadIdx.x;
    const int tx = tid & 15, ty = tid >> 4;
    const int arow = tid >> 2, acol = (tid & 3) << 2;
    const int brow = tid >> 4, bcol = (tid & 15) << 2;
    const int K = K1 + K2;
    const int nt = N >> 6;
    const int tiles = (M >> 6) * nt;
    for (int tile = blockIdx.x; tile < tiles; tile += gridDim.x) {
        int bm = (tile / nt) << 6, bn = (tile % nt) << 6;
        float acc[4][4] = {};
        for (int kb = 0; kb < K; kb += 16) {
            int k = kb + acol;
            const float* Ap; int ld, kk;
            if (k < K1) { Ap = A1; ld = lda1; kk = k; }
            else        { Ap = A2; ld = lda2; kk = k - K1; }
            float4 av = *reinterpret_cast<const float4*>(Ap + (size_t)(bm+arow)*ld + kk);
            As[arow][acol+0] = av.x; As[arow][acol+1] = av.y;
            As[arow][acol+2] = av.z; As[arow][acol+3] = av.w;
            *reinterpret_cast<float4*>(&Bs[brow][bcol]) =
                *reinterpret_cast<const float4*>(Bm + (size_t)(kb+brow)*N + bn + bcol);
            __syncthreads();
#pragma unroll
            for (int q = 0; q < 16; q++) {
                float a0 = As[(ty<<2)+0][q], a1 = As[(ty<<2)+1][q];
                float a2 = As[(ty<<2)+2][q], a3 = As[(ty<<2)+3][q];
                float4 b4 = *reinterpret_cast<const float4*>(&Bs[q][tx<<2]);
                acc[0][0]+=a0*b4.x; acc[0][1]+=a0*b4.y; acc[0][2]+=a0*b4.z; acc[0][3]+=a0*b4.w;
                acc[1][0]+=a1*b4.x; acc[1][1]+=a1*b4.y; acc[1][2]+=a1*b4.z; acc[1][3]+=a1*b4.w;
                acc[2][0]+=a2*b4.x; acc[2][1]+=a2*b4.y; acc[2][2]+=a2*b4.z; acc[2][3]+=a2*b4.w;
                acc[3][0]+=a3*b4.x; acc[3][1]+=a3*b4.y; acc[3][2]+=a3*b4.z; acc[3][3]+=a3*b4.w;
            }
            __syncthreads();
        }
#pragma unroll
        for (int i = 0; i < 4; i++) {
            int r = bm + (ty<<2) + i;
#pragma unroll
            for (int j = 0; j < 4; j++) {
                int cn = bn + (tx<<2) + j;
                C[(size_t)r*ldc + cn] = acc[i][j] + bias[cn];
            }
        }
    }
}

// ---------------- lstm pointwise ----------------
__device__ void lstm_point_phase(
    const float* __restrict__ gates, float* __restrict__ h, float* __restrict__ c,
    float* __restrict__ enc_out, int t, int gi0, int gstride)
{
    for (int i = gi0; i < Bn*Hn; i += gstride) {
        int b = i >> 7, u = i & 127;
        const float* g = gates + (size_t)b*512;
        float gi = g[u], gf = g[u+128], gg = g[u+256], go = g[u+384];
        float cc = sigf(gf)*c[i] + sigf(gi)*tanhf(gg);
        float hh = sigf(go)*tanhf(cc);
        c[i] = cc; h[i] = hh;
        if (enc_out) enc_out[(size_t)b*(Sn*Hn) + t*Hn + u] = hh;
    }
}

// ---------------- transpose [B][S][H] -> [B][H][S] ----------------
__device__ void transpose_phase(const float* __restrict__ in, float* __restrict__ out)
{
    __shared__ float tile[32][33];
    const int tid = threadIdx.x;
    int x = tid & 31, y = tid >> 5;
    for (int tt = blockIdx.x; tt < Bn*16; tt += gridDim.x) {
        int b = tt >> 4;
        int tr = (tt & 15) >> 2, tc = tt & 3;
        const float* ip = in  + (size_t)b*16384;
        float*       op = out + (size_t)b*16384;
#pragma unroll
        for (int i = 0; i < 32; i += 8)
            tile[y+i][x] = ip[(tr*32+y+i)*128 + tc*32 + x];
        __syncthreads();
#pragma unroll
        for (int i = 0; i < 32; i += 8)
            op[(tc*32+y+i)*128 + tr*32 + x] = tile[x][y+i];
        __syncthreads();
    }
}

// ---------------- glimpse (threads 0-127 active) ----------------
__device__ void glimpse_phase(
    const float* __restrict__ gref, const float* __restrict__ qg,
    const float* __restrict__ gV, const unsigned char* __restrict__ mask,
    float* __restrict__ q2, float* __restrict__ refs)
{
    __shared__ float qs[128], vs[128], red[128], pr[128];
    const int tid = threadIdx.x;
    const bool act = tid < 128;
    const int s = tid & 127;
    for (int b = blockIdx.x; b < Bn; b += gridDim.x) {
        if (act) { qs[s] = qg[b*128+s]; vs[s] = gV[s]; }
        __syncthreads();
        float gl = 0.f, acc = 0.f;
        if (act) {
            const float* rp = gref + (size_t)b*16384;
#pragma unroll 8
            for (int h = 0; h < 128; h++) {
                float r = rp[h*128+s];
                refs[h*128+s] = r;
                acc += vs[h]*tanhf(qs[h]+r);
            }
            gl = mask[b*128+s] ? __int_as_float(0xff800000) : acc;
            red[s] = gl;
        }
        __syncthreads();
#pragma unroll
        for (int off = 64; off > 0; off >>= 1) {
            if (act && s < off) red[s] = fmaxf(red[s], red[s+off]);
            __syncthreads();
        }
        float mx = red[0]; __syncthreads();
        float ex = 0.f;
        if (act) { ex = expf(gl - mx); red[s] = ex; }
        __syncthreads();
#pragma unroll
        for (int off = 64; off > 0; off >>= 1) {
            if (act && s < off) red[s] += red[s+off];
            __syncthreads();
        }
        if (act) pr[s] = ex / red[0];
        __syncthreads();
        if (act) {
            int lane = s & 31, w = s >> 5;
            for (int h = w; h < 128; h += 4) {
                const float* rr = refs + h*128;
                float v = rr[lane]*pr[lane] + rr[lane+32]*pr[lane+32]
                        + rr[lane+64]*pr[lane+64] + rr[lane+96]*pr[lane+96];
#pragma unroll
                for (int o = 16; o > 0; o >>= 1) v += __shfl_down_sync(0xffffffffu, v, o);
                if (lane == 0) q2[b*128+h] = v;
            }
        }
        __syncthreads();
    }
}

// ---------------- pointer (threads 0-127 active) ----------------
__device__ void pointer_phase(
    const float* __restrict__ pref, const float* __restrict__ qp,
    const float* __restrict__ pV, unsigned char* __restrict__ mask,
    const float* __restrict__ embedded,
    float* __restrict__ probs_out, float* __restrict__ idx_out,
    float* __restrict__ dec_in, int t)
{
    __shared__ float qs[128], vs[128], red[128];
    __shared__ int ri[128];
    __shared__ int sel;
    const int tid = threadIdx.x;
    const bool act = tid < 128;
    const int s = tid & 127;
    for (int b = blockIdx.x; b < Bn; b += gridDim.x) {
        if (act) { qs[s] = qp[b*128+s]; vs[s] = pV[s]; }
        __syncthreads();
        float pl = 0.f;
        if (act) {
            const float* rp = pref + (size_t)b*16384;
            float acc = 0.f;
#pragma unroll 8
            for (int h = 0; h < 128; h++)
                acc += vs[h]*tanhf(qs[h] + rp[h*128+s]);
            pl = 10.0f*tanhf(acc);
            if (mask[b*128+s]) pl = __int_as_float(0xff800000);
            red[s] = pl;
        }
        __syncthreads();
#pragma unroll
        for (int off = 64; off > 0; off >>= 1) {
            if (act && s < off) red[s] = fmaxf(red[s], red[s+off]);
            __syncthreads();
        }
        float mx = red[0]; __syncthreads();
        float ex = 0.f;
        if (act) { ex = expf(pl - mx); red[s] = ex; }
        __syncthreads();
#pragma unroll
        for (int off = 64; off > 0; off >>= 1) {
            if (act && s < off) red[s] += red[s+off];
            __syncthreads();
        }
        float ssum = red[0]; __syncthreads();
        if (act) {
            probs_out[(size_t)b*128+s] = ex / ssum;
            // JAX partitionable threefry (default since JAX>=0.5):
            // per-element 64-bit counter j: (o0,o1)=threefry(key,(0,j)); bits=o0^o1
            unsigned k0, k1, o0, o1;
            threefry2x32(0u, 42u, 0u, (unsigned)t, k0, k1);   // fold_in(key(42), t)
            unsigned j = (unsigned)(b*128 + s);
            threefry2x32(k0, k1, 0u, j, o0, o1);
            unsigned bits = o0 ^ o1;
            float f = __uint_as_float((bits >> 9) | 0x3f800000u) - 1.0f;
            const float TINY = 1.1754943508222875e-38f;
            float uu = fmaxf(TINY, f + TINY);
            float y = pl + (-logf(-logf(uu)));
            red[s] = y; ri[s] = s;
        }
        __syncthreads();
#pragma unroll
        for (int off = 64; off > 0; off >>= 1) {
            if (act && s < off) {
                float ov = red[s+off]; int oi = ri[s+off];
                if (ov > red[s] || (ov == red[s] && oi < ri[s])) { red[s] = ov; ri[s] = oi; }
            }
            __syncthreads();
        }
        if (tid == 0) {
            sel = ri[0];
            mask[b*128+sel] = 1;
            if (idx_out) idx_out[b] = (float)sel;
        }
        __syncthreads();
        if (act) dec_in[b*128+s] = embedded[(size_t)b*16384 + sel*128 + s];
        __syncthreads();
    }
}

// ---------------- the one persistent kernel ----------------
__global__ void __launch_bounds__(256) meganet(
    const float* __restrict__ inp, const float* __restrict__ emb,
    const float* __restrict__ eWih, const float* __restrict__ eWhh,
    const float* __restrict__ ebih, const float* __restrict__ ebhh,
    const float* __restrict__ dWih, const float* __restrict__ dWhh,
    const float* __restrict__ dbih, const float* __restrict__ dbhh,
    const float* __restrict__ gWq,  const float* __restrict__ gbq,
    const float* __restrict__ gWref,const float* __restrict__ gbref,
    const float* __restrict__ gV,
    const float* __restrict__ pWq,  const float* __restrict__ pbq,
    const float* __restrict__ pWref,const float* __restrict__ pbref,
    const float* __restrict__ pV,
    const float* __restrict__ startv,
    float* __restrict__ probs_base, float* __restrict__ idx_base)
{
    extern __shared__ float dynbuf[];   // 64KB glimpse refs
    const int gstride = gridDim.x * 256;
    const int gi0 = blockIdx.x * 256 + threadIdx.x;

    // ---- prep ----
    for (int i = gi0; i < 131072; i += gstride) {
        int k = i >> 9, j = i & 511;
        d_Wenc[i] = (k < 128) ? eWih[j*128+k] : eWhh[j*128+(k-128)];
        d_Wdec[i] = (k < 128) ? dWih[j*128+k] : dWhh[j*128+(k-128)];
    }
    for (int i = gi0; i < 512; i += gstride) {
        d_benc[i] = ebih[i] + ebhh[i];
        d_bdec[i] = dbih[i] + dbhh[i];
    }
    for (int i = gi0; i < 16384; i += gstride) {
        int e = i >> 7, hh = i & 127;
        d_WqgT[i] = gWq [hh*128+e];
        d_WqpT[i] = pWq [hh*128+e];
        d_WgrT[i] = gWref[hh*128+e];
        d_WprT[i] = pWref[hh*128+e];
    }
    for (int i = gi0; i < Bn*Sn*En; i += gstride) {
        int e = i & 127, s = (i >> 7) & 127, b = i >> 14;
        d_embedded[i] = inp[b*256+s]*emb[e] + inp[b*256+128+s]*emb[128+e];
    }
    for (int i = gi0; i < Bn*Hn; i += gstride) { d_h[i] = 0.f; d_c[i] = 0.f; }
    for (int i = gi0; i < Bn*Sn; i += gstride) { d_mask[i] = 0; d_decin[i] = startv[i & 127]; }
    grid_sync();

    // ---- encoder ----
    for (int t = 0; t < Sn; t++) {
        gemm_phase(d_embedded + t*128, Sn*En, d_h, Hn, d_Wenc, d_benc,
                   d_gates, 512, Bn, 512, 128, 128);
        grid_sync();
        lstm_point_phase(d_gates, d_h, d_c, d_enc, t, gi0, gstride);
        grid_sync();
    }

    // ---- ref projections ----
    gemm_phase(d_enc, 128, nullptr, 0, d_WgrT, gbref, d_tmp, 128,
               Bn*Sn, 128, 128, 0);
    grid_sync();
    transpose_phase(d_tmp, d_gref);
    grid_sync();
    gemm_phase(d_enc, 128, nullptr, 0, d_WprT, pbref, d_tmp, 128,
               Bn*Sn, 128, 128, 0);
    grid_sync();
    transpose_phase(d_tmp, d_pref);
    grid_sync();

    // ---- decoder ----
    for (int t = 0; t < Sn; t++) {
        gemm_phase(d_decin, 128, d_h, 128, d_Wdec, d_bdec,
                   d_gates, 512, Bn, 512, 128, 128);
        grid_sync();
        lstm_point_phase(d_gates, d_h, d_c, nullptr, 0, gi0, gstride);
        grid_sync();
        gemm_phase(d_h, 128, nullptr, 0, d_WqgT, gbq, d_qg, 128,
                   Bn, 128, 128, 0);
        grid_sync();
        glimpse_phase(d_gref, d_qg, gV, d_mask, d_q2, dynbuf);
        grid_sync();
        gemm_phase(d_q2, 128, nullptr, 0, d_WqpT, pbq, d_qp, 128,
                   Bn, 128, 128, 0);
        grid_sync();
        pointer_phase(d_pref, d_qp, pV, d_mask, d_embedded,
                      probs_base + (size_t)t*Bn*Sn,
                      idx_base ? idx_base + (size_t)t*Bn : nullptr,
                      d_decin, t);
        grid_sync();
    }
}

// ---------------- host ----------------
extern "C" void kernel_launch(void* const* d_in, const int* in_sizes, int n_in,
                              void* d_out, int out_size)
{
    const float* P[21];
    for (int i = 0; i < 21; i++) P[i] = (const float*)d_in[i];

    float* tmp; cudaGetSymbolAddress((void**)&tmp, d_tmp);
    float* out = (float*)d_out;
    const long long PROBS = (long long)Sn * Bn * Sn;
    float* probs_base; float* idx_base = nullptr;
    if ((long long)out_size >= PROBS) {
        probs_base = out;
        if ((long long)out_size >= PROBS + (long long)Sn * Bn) idx_base = out + PROBS;
    } else {
        probs_base = tmp;
        if (out_size >= Sn * Bn) idx_base = out;
    }

    int sm = 0;
    cudaDeviceGetAttribute(&sm, cudaDevAttrMultiProcessorCount, 0);
    if (sm <= 0) sm = 148;

    cudaFuncSetAttribute(meganet, cudaFuncAttributeMaxDynamicSharedMemorySize, 65536);
    meganet<<<sm, 256, 65536>>>(
        P[0], P[1], P[2], P[3], P[4], P[5], P[6], P[7], P[8], P[9],
        P[10], P[11], P[12], P[13], P[14], P[15], P[16], P[17], P[18], P[19],
        P[20], probs_base, idx_base);
}

// round 17
// speedup vs baseline: 3.4899x; 3.4899x over previous
#include <cuda_runtime.h>
#include <cstdint>

#define Bn 2048
#define Sn 128
#define Hn 128
#define En 128

// ---------------- device scratch ----------------
__device__ float d_embedded[Bn*Sn*En];
__device__ float d_enc[Bn*Sn*Hn];
__device__ float d_tmp[Bn*Sn*Hn];
__device__ float d_gref[Bn*Hn*Sn];
__device__ float d_pref[Bn*Hn*Sn];
__device__ float d_h[Bn*Hn];
__device__ float d_c[Bn*Hn];
__device__ float d_gates[Bn*4*Hn];
__device__ float d_qg[Bn*Hn];
__device__ float d_q2[Bn*Hn];
__device__ float d_qp[Bn*Hn];
__device__ float d_decin[Bn*En];
__device__ unsigned char d_mask[Bn*Sn];
__device__ float d_Wenc[256*512];
__device__ float d_Wdec[256*512];
__device__ float d_benc[512];
__device__ float d_bdec[512];
__device__ float d_WqgT[128*128];
__device__ float d_WqpT[128*128];
__device__ float d_WgrT[128*128];
__device__ float d_WprT[128*128];
__device__ unsigned d_bar_arrive = 0;
__device__ unsigned d_bar_gen = 0;

// ---------------- helpers ----------------
__device__ __forceinline__ float sigf(float x){ return 1.0f/(1.0f+expf(-x)); }

__device__ __forceinline__ void threefry2x32(unsigned k0, unsigned k1,
                                             unsigned x0, unsigned x1,
                                             unsigned &o0, unsigned &o1)
{
    unsigned ks2 = k0 ^ k1 ^ 0x1BD11BDAu;
    x0 += k0; x1 += k1;
#define TF_R(r) { x0 += x1; x1 = (x1 << (r)) | (x1 >> (32-(r))); x1 ^= x0; }
    TF_R(13) TF_R(15) TF_R(26) TF_R(6)
    x0 += k1;  x1 += ks2 + 1u;
    TF_R(17) TF_R(29) TF_R(16) TF_R(24)
    x0 += ks2; x1 += k0 + 2u;
    TF_R(13) TF_R(15) TF_R(26) TF_R(6)
    x0 += k0;  x1 += k1 + 3u;
    TF_R(17) TF_R(29) TF_R(16) TF_R(24)
    x0 += k1;  x1 += ks2 + 4u;
    TF_R(13) TF_R(15) TF_R(26) TF_R(6)
    x0 += ks2; x1 += k0 + 5u;
#undef TF_R
    o0 = x0; o1 = x1;
}

// grid barrier — all blocks resident (grid = 4 x #SMs, forced 4 blocks/SM)
__device__ __forceinline__ void grid_sync()
{
    __syncthreads();
    if (threadIdx.x == 0) {
        unsigned gen;
        asm volatile("ld.acquire.gpu.u32 %0, [%1];" : "=r"(gen)
                     : "l"(&d_bar_gen) : "memory");
        __threadfence();                       // release my block's writes
        unsigned prev = atomicAdd(&d_bar_arrive, 1u);
        if (prev == gridDim.x - 1) {
            atomicExch(&d_bar_arrive, 0u);
            asm volatile("st.release.gpu.u32 [%0], %1;" ::
                         "l"(&d_bar_gen), "r"(gen + 1u) : "memory");
        } else {
            unsigned cur;
            do {
                asm volatile("ld.acquire.gpu.u32 %0, [%1];" : "=r"(cur)
                             : "l"(&d_bar_gen) : "memory");
            } while (cur == gen);
        }
    }
    __syncthreads();
    __threadfence();   // order/invalidate so post-barrier loads are fresh
}

// ---------------- gemm phase: C = [A1|A2] * B + bias ----------------
__device__ void gemm_phase(
    const float* __restrict__ A1, int lda1,
    const float* __restrict__ A2, int lda2,
    const float* __restrict__ Bm, const float* __restrict__ bias,
    float* __restrict__ C, int ldc,
    int M, int N, int K1, int K2)
{
    __shared__ float As[64][17];
    __shared__ __align__(16) float Bs[16][64];
    const int tid = threadIdx.x;
    const int tx = tid & 15, ty = tid >> 4;
    const int arow = tid >> 2, acol = (tid & 3) << 2;
    const int brow = tid >> 4, bcol = (tid & 15) << 2;
    const int K = K1 + K2;
    const int nt = N >> 6;
    const int tiles = (M >> 6) * nt;
    for (int tile = blockIdx.x; tile < tiles; tile += gridDim.x) {
        int bm = (tile / nt) << 6, bn = (tile % nt) << 6;
        float acc[4][4] = {};
        for (int kb = 0; kb < K; kb += 16) {
            int k = kb + acol;
            const float* Ap; int ld, kk;
            if (k < K1) { Ap = A1; ld = lda1; kk = k; }
            else        { Ap = A2; ld = lda2; kk = k - K1; }
            float4 av = *reinterpret_cast<const float4*>(Ap + (size_t)(bm+arow)*ld + kk);
            As[arow][acol+0] = av.x; As[arow][acol+1] = av.y;
            As[arow][acol+2] = av.z; As[arow][acol+3] = av.w;
            *reinterpret_cast<float4*>(&Bs[brow][bcol]) =
                *reinterpret_cast<const float4*>(Bm + (size_t)(kb+brow)*N + bn + bcol);
            __syncthreads();
#pragma unroll
            for (int q = 0; q < 16; q++) {
                float a0 = As[(ty<<2)+0][q], a1 = As[(ty<<2)+1][q];
                float a2 = As[(ty<<2)+2][q], a3 = As[(ty<<2)+3][q];
                float4 b4 = *reinterpret_cast<const float4*>(&Bs[q][tx<<2]);
                acc[0][0]+=a0*b4.x; acc[0][1]+=a0*b4.y; acc[0][2]+=a0*b4.z; acc[0][3]+=a0*b4.w;
                acc[1][0]+=a1*b4.x; acc[1][1]+=a1*b4.y; acc[1][2]+=a1*b4.z; acc[1][3]+=a1*b4.w;
                acc[2][0]+=a2*b4.x; acc[2][1]+=a2*b4.y; acc[2][2]+=a2*b4.z; acc[2][3]+=a2*b4.w;
                acc[3][0]+=a3*b4.x; acc[3][1]+=a3*b4.y; acc[3][2]+=a3*b4.z; acc[3][3]+=a3*b4.w;
            }
            __syncthreads();
        }
#pragma unroll
        for (int i = 0; i < 4; i++) {
            int r = bm + (ty<<2) + i;
#pragma unroll
            for (int j = 0; j < 4; j++) {
                int cn = bn + (tx<<2) + j;
                C[(size_t)r*ldc + cn] = acc[i][j] + bias[cn];
            }
        }
    }
}

// ---------------- lstm pointwise ----------------
__device__ void lstm_point_phase(
    const float* __restrict__ gates, float* __restrict__ h, float* __restrict__ c,
    float* __restrict__ enc_out, int t, int gi0, int gstride)
{
    for (int i = gi0; i < Bn*Hn; i += gstride) {
        int b = i >> 7, u = i & 127;
        const float* g = gates + (size_t)b*512;
        float gi = g[u], gf = g[u+128], gg = g[u+256], go = g[u+384];
        float cc = sigf(gf)*c[i] + sigf(gi)*tanhf(gg);
        float hh = sigf(go)*tanhf(cc);
        c[i] = cc; h[i] = hh;
        if (enc_out) enc_out[(size_t)b*(Sn*Hn) + t*Hn + u] = hh;
    }
}

// ---------------- transpose [B][S][H] -> [B][H][S] ----------------
__device__ void transpose_phase(const float* __restrict__ in, float* __restrict__ out)
{
    __shared__ float tile[32][33];
    const int tid = threadIdx.x;
    int x = tid & 31, y = tid >> 5;
    for (int tt = blockIdx.x; tt < Bn*16; tt += gridDim.x) {
        int b = tt >> 4;
        int tr = (tt & 15) >> 2, tc = tt & 3;
        const float* ip = in  + (size_t)b*16384;
        float*       op = out + (size_t)b*16384;
#pragma unroll
        for (int i = 0; i < 32; i += 8)
            tile[y+i][x] = ip[(tr*32+y+i)*128 + tc*32 + x];
        __syncthreads();
#pragma unroll
        for (int i = 0; i < 32; i += 8)
            op[(tc*32+y+i)*128 + tr*32 + x] = tile[x][y+i];
        __syncthreads();
    }
}

// ---------------- glimpse (threads 0-127 active; gref read from L2 twice) ----
__device__ void glimpse_phase(
    const float* __restrict__ gref, const float* __restrict__ qg,
    const float* __restrict__ gV, const unsigned char* __restrict__ mask,
    float* __restrict__ q2)
{
    __shared__ float qs[128], vs[128], red[128], pr[128];
    const int tid = threadIdx.x;
    const bool act = tid < 128;
    const int s = tid & 127;
    for (int b = blockIdx.x; b < Bn; b += gridDim.x) {
        if (act) { qs[s] = qg[b*128+s]; vs[s] = gV[s]; }
        __syncthreads();
        float gl = 0.f, acc = 0.f;
        const float* rp = gref + (size_t)b*16384;
        if (act) {
#pragma unroll 8
            for (int h = 0; h < 128; h++)
                acc += vs[h]*tanhf(qs[h] + rp[h*128+s]);
            gl = mask[b*128+s] ? __int_as_float(0xff800000) : acc;
            red[s] = gl;
        }
        __syncthreads();
#pragma unroll
        for (int off = 64; off > 0; off >>= 1) {
            if (act && s < off) red[s] = fmaxf(red[s], red[s+off]);
            __syncthreads();
        }
        float mx = red[0]; __syncthreads();
        float ex = 0.f;
        if (act) { ex = expf(gl - mx); red[s] = ex; }
        __syncthreads();
#pragma unroll
        for (int off = 64; off > 0; off >>= 1) {
            if (act && s < off) red[s] += red[s+off];
            __syncthreads();
        }
        if (act) pr[s] = ex / red[0];
        __syncthreads();
        if (act) {
            int lane = s & 31, w = s >> 5;
            for (int h = w; h < 128; h += 4) {
                const float* rr = rp + h*128;      // same values as R15's smem copy
                float v = rr[lane]*pr[lane] + rr[lane+32]*pr[lane+32]
                        + rr[lane+64]*pr[lane+64] + rr[lane+96]*pr[lane+96];
#pragma unroll
                for (int o = 16; o > 0; o >>= 1) v += __shfl_down_sync(0xffffffffu, v, o);
                if (lane == 0) q2[b*128+h] = v;
            }
        }
        __syncthreads();
    }
}

// ---------------- pointer (threads 0-127 active) ----------------
__device__ void pointer_phase(
    const float* __restrict__ pref, const float* __restrict__ qp,
    const float* __restrict__ pV, unsigned char* __restrict__ mask,
    const float* __restrict__ embedded,
    float* __restrict__ probs_out, float* __restrict__ idx_out,
    float* __restrict__ dec_in, int t)
{
    __shared__ float qs[128], vs[128], red[128];
    __shared__ int ri[128];
    __shared__ int sel;
    const int tid = threadIdx.x;
    const bool act = tid < 128;
    const int s = tid & 127;
    for (int b = blockIdx.x; b < Bn; b += gridDim.x) {
        if (act) { qs[s] = qp[b*128+s]; vs[s] = pV[s]; }
        __syncthreads();
        float pl = 0.f;
        if (act) {
            const float* rp = pref + (size_t)b*16384;
            float acc = 0.f;
#pragma unroll 8
            for (int h = 0; h < 128; h++)
                acc += vs[h]*tanhf(qs[h] + rp[h*128+s]);
            pl = 10.0f*tanhf(acc);
            if (mask[b*128+s]) pl = __int_as_float(0xff800000);
            red[s] = pl;
        }
        __syncthreads();
#pragma unroll
        for (int off = 64; off > 0; off >>= 1) {
            if (act && s < off) red[s] = fmaxf(red[s], red[s+off]);
            __syncthreads();
        }
        float mx = red[0]; __syncthreads();
        float ex = 0.f;
        if (act) { ex = expf(pl - mx); red[s] = ex; }
        __syncthreads();
#pragma unroll
        for (int off = 64; off > 0; off >>= 1) {
            if (act && s < off) red[s] += red[s+off];
            __syncthreads();
        }
        float ssum = red[0]; __syncthreads();
        if (act) {
            probs_out[(size_t)b*128+s] = ex / ssum;
            // JAX partitionable threefry: bits = o0 ^ o1 of threefry(key,(0,j))
            unsigned k0, k1, o0, o1;
            threefry2x32(0u, 42u, 0u, (unsigned)t, k0, k1);
            unsigned j = (unsigned)(b*128 + s);
            threefry2x32(k0, k1, 0u, j, o0, o1);
            unsigned bits = o0 ^ o1;
            float f = __uint_as_float((bits >> 9) | 0x3f800000u) - 1.0f;
            const float TINY = 1.1754943508222875e-38f;
            float uu = fmaxf(TINY, f + TINY);
            float y = pl + (-logf(-logf(uu)));
            red[s] = y; ri[s] = s;
        }
        __syncthreads();
#pragma unroll
        for (int off = 64; off > 0; off >>= 1) {
            if (act && s < off) {
                float ov = red[s+off]; int oi = ri[s+off];
                if (ov > red[s] || (ov == red[s] && oi < ri[s])) { red[s] = ov; ri[s] = oi; }
            }
            __syncthreads();
        }
        if (tid == 0) {
            sel = ri[0];
            mask[b*128+sel] = 1;
            if (idx_out) idx_out[b] = (float)sel;
        }
        __syncthreads();
        if (act) dec_in[b*128+s] = embedded[(size_t)b*16384 + sel*128 + s];
        __syncthreads();
    }
}

// ---------------- the one persistent kernel ----------------
__global__ void __launch_bounds__(256, 4) meganet(
    const float* __restrict__ inp, const float* __restrict__ emb,
    const float* __restrict__ eWih, const float* __restrict__ eWhh,
    const float* __restrict__ ebih, const float* __restrict__ ebhh,
    const float* __restrict__ dWih, const float* __restrict__ dWhh,
    const float* __restrict__ dbih, const float* __restrict__ dbhh,
    const float* __restrict__ gWq,  const float* __restrict__ gbq,
    const float* __restrict__ gWref,const float* __restrict__ gbref,
    const float* __restrict__ gV,
    const float* __restrict__ pWq,  const float* __restrict__ pbq,
    const float* __restrict__ pWref,const float* __restrict__ pbref,
    const float* __restrict__ pV,
    const float* __restrict__ startv,
    float* __restrict__ probs_base, float* __restrict__ idx_base)
{
    const int gstride = gridDim.x * 256;
    const int gi0 = blockIdx.x * 256 + threadIdx.x;

    // ---- prep ----
    for (int i = gi0; i < 131072; i += gstride) {
        int k = i >> 9, j = i & 511;
        d_Wenc[i] = (k < 128) ? eWih[j*128+k] : eWhh[j*128+(k-128)];
        d_Wdec[i] = (k < 128) ? dWih[j*128+k] : dWhh[j*128+(k-128)];
    }
    for (int i = gi0; i < 512; i += gstride) {
        d_benc[i] = ebih[i] + ebhh[i];
        d_bdec[i] = dbih[i] + dbhh[i];
    }
    for (int i = gi0; i < 16384; i += gstride) {
        int e = i >> 7, hh = i & 127;
        d_WqgT[i] = gWq [hh*128+e];
        d_WqpT[i] = pWq [hh*128+e];
        d_WgrT[i] = gWref[hh*128+e];
        d_WprT[i] = pWref[hh*128+e];
    }
    for (int i = gi0; i < Bn*Sn*En; i += gstride) {
        int e = i & 127, s = (i >> 7) & 127, b = i >> 14;
        d_embedded[i] = inp[b*256+s]*emb[e] + inp[b*256+128+s]*emb[128+e];
    }
    for (int i = gi0; i < Bn*Hn; i += gstride) { d_h[i] = 0.f; d_c[i] = 0.f; }
    for (int i = gi0; i < Bn*Sn; i += gstride) { d_mask[i] = 0; d_decin[i] = startv[i & 127]; }
    grid_sync();

    // ---- encoder ----
    for (int t = 0; t < Sn; t++) {
        gemm_phase(d_embedded + t*128, Sn*En, d_h, Hn, d_Wenc, d_benc,
                   d_gates, 512, Bn, 512, 128, 128);
        grid_sync();
        lstm_point_phase(d_gates, d_h, d_c, d_enc, t, gi0, gstride);
        grid_sync();
    }

    // ---- ref projections ----
    gemm_phase(d_enc, 128, nullptr, 0, d_WgrT, gbref, d_tmp, 128,
               Bn*Sn, 128, 128, 0);
    grid_sync();
    transpose_phase(d_tmp, d_gref);
    grid_sync();
    gemm_phase(d_enc, 128, nullptr, 0, d_WprT, pbref, d_tmp, 128,
               Bn*Sn, 128, 128, 0);
    grid_sync();
    transpose_phase(d_tmp, d_pref);
    grid_sync();

    // ---- decoder ----
    for (int t = 0; t < Sn; t++) {
        gemm_phase(d_decin, 128, d_h, 128, d_Wdec, d_bdec,
                   d_gates, 512, Bn, 512, 128, 128);
        grid_sync();
        lstm_point_phase(d_gates, d_h, d_c, nullptr, 0, gi0, gstride);
        grid_sync();
        gemm_phase(d_h, 128, nullptr, 0, d_WqgT, gbq, d_qg, 128,
                   Bn, 128, 128, 0);
        grid_sync();
        glimpse_phase(d_gref, d_qg, gV, d_mask, d_q2);
        grid_sync();
        gemm_phase(d_q2, 128, nullptr, 0, d_WqpT, pbq, d_qp, 128,
                   Bn, 128, 128, 0);
        grid_sync();
        pointer_phase(d_pref, d_qp, pV, d_mask, d_embedded,
                      probs_base + (size_t)t*Bn*Sn,
                      idx_base ? idx_base + (size_t)t*Bn : nullptr,
                      d_decin, t);
        grid_sync();
    }
}

// ---------------- host ----------------
extern "C" void kernel_launch(void* const* d_in, const int* in_sizes, int n_in,
                              void* d_out, int out_size)
{
    const float* P[21];
    for (int i = 0; i < 21; i++) P[i] = (const float*)d_in[i];

    float* tmp; cudaGetSymbolAddress((void**)&tmp, d_tmp);
    float* out = (float*)d_out;
    const long long PROBS = (long long)Sn * Bn * Sn;
    float* probs_base; float* idx_base = nullptr;
    if ((long long)out_size >= PROBS) {
        probs_base = out;
        if ((long long)out_size >= PROBS + (long long)Sn * Bn) idx_base = out + PROBS;
    } else {
        probs_base = tmp;
        if (out_size >= Sn * Bn) idx_base = out;
    }

    int sm = 0;
    cudaDeviceGetAttribute(&sm, cudaDevAttrMultiProcessorCount, 0);
    if (sm <= 0) sm = 148;

    meganet<<<sm * 4, 256>>>(
        P[0], P[1], P[2], P[3], P[4], P[5], P[6], P[7], P[8], P[9],
        P[10], P[11], P[12], P[13], P[14], P[15], P[16], P[17], P[18], P[19],
        P[20], probs_base, idx_base);
}